// round 16
// baseline (speedup 1.0000x reference)
#include <cuda_runtime.h>
#include <cuda_bf16.h>
#include <cstdint>

// ---------------------------------------------------------------------------
// AbstractGenerativeUpsample — R14: split-bf16 HMMA, 4-stage cp.async pipeline
//   fea[50000,256] f32, W_up[8,256,256] f32, b_up[256], W_cls[256,1], b_cls[1]
//   target_idx[200000] int64 (or int32; runtime-detected)
// Output (concat f32): fea_pruned[400000,256] | exist[400000] | target[400000]
//
// 4 launches: fused_pre -> exist_split -> scatter -> GEMM (ncu capture slot 3).
// GEMM: fea_up = fea @ W_k via Ahi*Bhi + Ahi*Blo + Alo*Bhi (bf16 split, fp32
// accumulate; residual ~1e-5). keep from exact fp32 de-fused exist path.
// ---------------------------------------------------------------------------

#define NPAR  50000
#define CIN   256
#define COUT  256
#define FAN   8
#define NUP   (NPAR * FAN)          // 400000
#define NTGT  200000
#define FEA_ELEMS 102400000LL

#define BM 128
#define BN 128
#define BK 16                        // bf16 per pipeline stage
#define NITER (CIN / BK)             // 16
#define NSTAGE 4
#define MTILES ((NPAR + BM - 1) / BM)  // 391

// Padded smem rows: 24 bf16 = 48B stride -> ldmatrix conflict-free
// (8 rows x 48B: 16B segments {0,3,6,1,4,7,2,5} mod 128 -> distinct)
#define ASTR  24
#define TILEB (128 * ASTR * 2)       // 6144 B per tile (128 rows x 48B)
#define STAGEB (4 * TILEB)           // Ahi|Alo|Bhi|Blo = 24576 B
#define SM_KEEP (NSTAGE * STAGEB)    // 98304
#define SMEM_TOTAL (SM_KEEP + 512)   // 98816  (x2 CTAs = 193 KB <= 228 KB)

// ------------------------- device scratch (no allocs) ----------------------
__device__ __align__(256) __nv_bfloat16 g_fea_hi[NPAR * CIN];
__device__ __align__(256) __nv_bfloat16 g_fea_lo[NPAR * CIN];
__device__ __align__(256) __nv_bfloat16 g_wt_hi[FAN * COUT * CIN];  // [k][n][c]
__device__ __align__(256) __nv_bfloat16 g_wt_lo[FAN * COUT * CIN];
__device__ float         g_Wv[FAN * COUT];
__device__ float         g_c0;
__device__ unsigned char g_keep[NUP];
__device__ int           g_idx_stride;

// ------------------------------ helpers ------------------------------------
__device__ __forceinline__ uint32_t smem_u32(const void* p) {
    uint32_t a;
    asm("{ .reg .u64 t; cvta.to.shared.u64 t, %1; cvt.u32.u64 %0, t; }"
        : "=r"(a) : "l"(p));
    return a;
}
__device__ __forceinline__ void cp16(uint32_t smem_dst, const void* gsrc) {
    asm volatile("cp.async.cg.shared.global [%0], [%1], 16;\n"
                 :: "r"(smem_dst), "l"(gsrc));
}
__device__ __forceinline__ void cp_commit() {
    asm volatile("cp.async.commit_group;\n" ::: "memory");
}
template <int N>
__device__ __forceinline__ void cp_wait() {
    asm volatile("cp.async.wait_group %0;\n" :: "n"(N) : "memory");
}
__device__ __forceinline__ void ldsm_x4(uint32_t* r, uint32_t addr) {
    asm volatile("ldmatrix.sync.aligned.m8n8.x4.shared.b16 {%0,%1,%2,%3}, [%4];"
                 : "=r"(r[0]), "=r"(r[1]), "=r"(r[2]), "=r"(r[3]) : "r"(addr));
}
__device__ __forceinline__ void mma_bf16(float* d, const uint32_t* a,
                                         const uint32_t* b) {
    asm volatile(
        "mma.sync.aligned.m16n8k16.row.col.f32.bf16.bf16.f32 "
        "{%0,%1,%2,%3}, {%4,%5,%6,%7}, {%8,%9}, {%0,%1,%2,%3};"
        : "+f"(d[0]), "+f"(d[1]), "+f"(d[2]), "+f"(d[3])
        : "r"(a[0]), "r"(a[1]), "r"(a[2]), "r"(a[3]), "r"(b[0]), "r"(b[1]));
}

// ------------- fused pre-kernel: detect | c0 | Wv | split_w ----------------
__global__ void fused_pre_kernel(const float* __restrict__ Wup,
                                 const float* __restrict__ Wcls,
                                 const float* __restrict__ bup,
                                 const float* __restrict__ bcls,
                                 const int* __restrict__ idx32) {
    __shared__ float sW[COUT];
    const int tid = threadIdx.x;
    const int bx = blockIdx.x;
    if (bx == 0) {
        if (tid == 0) {
            int allzero = 1;
            #pragma unroll 1
            for (int i = 0; i < 64; i++) {
                if (idx32[2 * (i * 512) + 1] != 0) { allzero = 0; break; }
            }
            g_idx_stride = allzero ? 2 : 1;
        } else if (tid >= 32 && tid < 64) {
            const int lane = tid - 32;
            float p = 0.0f;
            #pragma unroll
            for (int j = 0; j < 8; j++)
                p = fmaf(bup[lane + 32 * j], Wcls[lane + 32 * j], p);
            #pragma unroll
            for (int off = 16; off > 0; off >>= 1)
                p += __shfl_xor_sync(0xFFFFFFFFu, p, off);
            if (lane == 0) g_c0 = p + bcls[0];
        }
        return;
    }
    if (bx <= 256) {                         // Wv[k][c] = Wk[c][:] . Wcls
        const int b = bx - 1;
        if (tid < COUT) sW[tid] = Wcls[tid];
        __syncthreads();
        const int k = b >> 5;
        const int c = ((b & 31) << 3) + (tid >> 5);
        const int lane = tid & 31;
        const float* row = Wup + ((size_t)k * COUT + c) * CIN;
        float p = 0.0f;
        #pragma unroll
        for (int j = 0; j < 8; j++)
            p = fmaf(row[lane + 32 * j], sW[lane + 32 * j], p);
        #pragma unroll
        for (int off = 16; off > 0; off >>= 1)
            p += __shfl_xor_sync(0xFFFFFFFFu, p, off);
        if (lane == 0) g_Wv[k * COUT + c] = p;
        return;
    }
    // split_w: Wt[k][n][c] = split(W[k][c][n]); blocks 257..768
    const int base = (bx - 257) * 1024 + tid * 4;
    #pragma unroll
    for (int j = 0; j < 4; j++) {
        int t = base + j;
        int k = t >> 16, r = t & 65535, n = r >> 8, c = r & 255;
        float x = Wup[(k << 16) + (c << 8) + n];
        __nv_bfloat16 hi = __float2bfloat16_rn(x);
        __nv_bfloat16 lo = __float2bfloat16_rn(x - __bfloat162float(hi));
        g_wt_hi[t] = hi;
        g_wt_lo[t] = lo;
    }
}

// ---- exist (+keep, +tgt zero) fused with fea hi/lo split: one fea read ----
__global__ __launch_bounds__(256)
void exist_split_kernel(const float* __restrict__ fea,
                        float* __restrict__ out_exist,
                        float* __restrict__ out_tgt) {
    __shared__ float sWv[FAN * COUT];
    const int tid = threadIdx.x;
    #pragma unroll
    for (int j = 0; j < FAN * COUT / 256; j++) sWv[tid + 256 * j] = g_Wv[tid + 256 * j];
    __syncthreads();
    const int w = tid >> 5, lane = tid & 31;
    const int n = blockIdx.x * 8 + w;
    const float c0 = g_c0;
    float f[8];
    const float* frow = fea + (size_t)n * CIN;
    #pragma unroll
    for (int j = 0; j < 8; j++) f[j] = frow[lane + 32 * j];
    #pragma unroll
    for (int j = 0; j < 8; j++) {
        __nv_bfloat16 hi = __float2bfloat16_rn(f[j]);
        __nv_bfloat16 lo = __float2bfloat16_rn(f[j] - __bfloat162float(hi));
        g_fea_hi[(size_t)n * CIN + lane + 32 * j] = hi;
        g_fea_lo[(size_t)n * CIN + lane + 32 * j] = lo;
    }
    float mye = 0.0f;
    #pragma unroll
    for (int k = 0; k < FAN; k++) {
        float p = 0.0f;
        #pragma unroll
        for (int j = 0; j < 8; j++) p = fmaf(f[j], sWv[k * COUT + lane + 32 * j], p);
        #pragma unroll
        for (int off = 16; off > 0; off >>= 1)
            p += __shfl_xor_sync(0xFFFFFFFFu, p, off);
        if (lane == k) mye = p + c0;
    }
    if (lane < FAN) {
        const size_t g = (size_t)n * FAN + lane;
        out_exist[g] = mye;
        out_tgt[g] = 0.0f;
        g_keep[g] = (mye > 0.0f) ? 1 : 0;
    }
}

// ----------------------------- target scatter ------------------------------
__global__ void scatter_target_kernel(const int* __restrict__ idx32,
                                      float* __restrict__ tgt) {
    int i = blockIdx.x * blockDim.x + threadIdx.x;
    if (i < NTGT) {
        int s = g_idx_stride;
        int v = idx32[i * s];
        if (v >= 0 && v < NUP) { tgt[v] = 1.0f; g_keep[v] = 1; }
    }
}

// --------------------------- main HMMA GEMM --------------------------------
// grid (16, 391): bx -> {k = bx&7, ntile = bx>>3}; by = m tile. 256 threads,
// 8 warps as 4x2 -> warp tile 32x64. 4-stage cp.async pipeline, BK=16,
// one __syncthreads per iteration; accumulator RAW chains distance-4.
__global__ __launch_bounds__(256, 2)
void upsample_hmma_kernel(const float* __restrict__ bup,
                          float* __restrict__ out_fea) {
    extern __shared__ __align__(1024) char smem[];
    const uint32_t sb = smem_u32(smem);
    const int tid  = threadIdx.x;
    const int wid  = tid >> 5;
    const int lane = tid & 31;
    const int k    = blockIdx.x & 7;
    const int bn   = (blockIdx.x >> 3) * BN;
    const int nb   = blockIdx.y * BM;

    const int warp_m = (wid >> 1) * 32;
    const int warp_n = (wid & 1) * 64;

    float* sKeep = (float*)(smem + SM_KEEP);
    if (tid < BM) {
        const int n = nb + tid;
        sKeep[tid] = (n < NPAR && g_keep[(size_t)n * FAN + k]) ? 1.0f : 0.0f;
    }

    // ---- staging map: thread -> one 16B slot per tile ----
    const int srow = tid >> 1;               // 0..127
    const int c16  = tid & 1;                // 0..1
    int an = nb + srow; if (an >= NPAR) an = NPAR - 1;
    const size_t aoff = (size_t)an * CIN + c16 * 8;
    const size_t boff = ((size_t)k * COUT + bn + srow) * CIN + c16 * 8;
    const uint32_t sd = srow * (ASTR * 2) + c16 * 16;

    float acc[2][8][4];
    #pragma unroll
    for (int mt = 0; mt < 2; mt++)
        #pragma unroll
        for (int nt = 0; nt < 8; nt++)
            #pragma unroll
            for (int j = 0; j < 4; j++) acc[mt][nt][j] = 0.0f;

    // ---- prologue: stage chunks 0..2 ----
    #pragma unroll
    for (int ts = 0; ts < NSTAGE - 1; ts++) {
        const uint32_t dst = sb + (uint32_t)ts * STAGEB;
        const size_t kc = (size_t)ts * BK;
        cp16(dst + sd,             g_fea_hi + aoff + kc);
        cp16(dst + TILEB + sd,     g_fea_lo + aoff + kc);
        cp16(dst + 2 * TILEB + sd, g_wt_hi + boff + kc);
        cp16(dst + 3 * TILEB + sd, g_wt_lo + boff + kc);
        cp_commit();
    }

    // ldmatrix lane address components (element units)
    const int a_row = (lane & 15);
    const int a_kh  = ((lane >> 4) & 1) * 8;
    const int b_row = (lane & 7) + ((lane >> 4) & 1) * 8;
    const int b_kh  = ((lane >> 3) & 1) * 8;

    #pragma unroll 1
    for (int t = 0; t < NITER; t++) {
        cp_wait<NSTAGE - 2>();               // chunk t resident
        __syncthreads();
        const uint32_t base = sb + (uint32_t)(t & (NSTAGE - 1)) * STAGEB;

        // A fragments for this k-slab
        uint32_t ah[2][4], al[2][4];
        #pragma unroll
        for (int mt = 0; mt < 2; mt++) {
            const uint32_t ao = ((warp_m + mt * 16 + a_row) * ASTR + a_kh) * 2;
            ldsm_x4(ah[mt], base + ao);
            ldsm_x4(al[mt], base + TILEB + ao);
        }

        // first n-half: p = 0,1 (tensor starts immediately)
        #pragma unroll
        for (int p = 0; p < 2; p++) {
            uint32_t bh[4], bl[4];
            const uint32_t bo = ((warp_n + p * 16 + b_row) * ASTR + b_kh) * 2;
            ldsm_x4(bh, base + 2 * TILEB + bo);
            ldsm_x4(bl, base + 3 * TILEB + bo);
            #pragma unroll
            for (int mt = 0; mt < 2; mt++)
                #pragma unroll
                for (int half = 0; half < 2; half++)
                    mma_bf16(acc[mt][2 * p + half], ah[mt], &bh[2 * half]);
            #pragma unroll
            for (int mt = 0; mt < 2; mt++)
                #pragma unroll
                for (int half = 0; half < 2; half++)
                    mma_bf16(acc[mt][2 * p + half], ah[mt], &bl[2 * half]);
            #pragma unroll
            for (int mt = 0; mt < 2; mt++)
                #pragma unroll
                for (int half = 0; half < 2; half++)
                    mma_bf16(acc[mt][2 * p + half], al[mt], &bh[2 * half]);
        }

        // stage chunk t+3 (overwrites slot of t-1; safe after this iter's sync)
        if (t + NSTAGE - 1 < NITER) {
            const int ts = t + NSTAGE - 1;
            const uint32_t dst = sb + (uint32_t)(ts & (NSTAGE - 1)) * STAGEB;
            const size_t kc = (size_t)ts * BK;
            cp16(dst + sd,             g_fea_hi + aoff + kc);
            cp16(dst + TILEB + sd,     g_fea_lo + aoff + kc);
            cp16(dst + 2 * TILEB + sd, g_wt_hi + boff + kc);
            cp16(dst + 3 * TILEB + sd, g_wt_lo + boff + kc);
        }
        cp_commit();                         // uniform group accounting

        // second n-half: p = 2,3
        #pragma unroll
        for (int p = 2; p < 4; p++) {
            uint32_t bh[4], bl[4];
            const uint32_t bo = ((warp_n + p * 16 + b_row) * ASTR + b_kh) * 2;
            ldsm_x4(bh, base + 2 * TILEB + bo);
            ldsm_x4(bl, base + 3 * TILEB + bo);
            #pragma unroll
            for (int mt = 0; mt < 2; mt++)
                #pragma unroll
                for (int half = 0; half < 2; half++)
                    mma_bf16(acc[mt][2 * p + half], ah[mt], &bh[2 * half]);
            #pragma unroll
            for (int mt = 0; mt < 2; mt++)
                #pragma unroll
                for (int half = 0; half < 2; half++)
                    mma_bf16(acc[mt][2 * p + half], ah[mt], &bl[2 * half]);
            #pragma unroll
            for (int mt = 0; mt < 2; mt++)
                #pragma unroll
                for (int half = 0; half < 2; half++)
                    mma_bf16(acc[mt][2 * p + half], al[mt], &bh[2 * half]);
        }
    }

    // ---- epilogue: +b_up, mask by keep, store ----
    float2 bb[8];
    #pragma unroll
    for (int nt = 0; nt < 8; nt++)
        bb[nt] = *reinterpret_cast<const float2*>(
            bup + bn + warp_n + nt * 8 + (lane & 3) * 2);

    #pragma unroll
    for (int mt = 0; mt < 2; mt++)
        #pragma unroll
        for (int h = 0; h < 2; h++) {
            const int row = warp_m + mt * 16 + (lane >> 2) + h * 8;
            const int n = nb + row;
            if (n >= NPAR) continue;
            const float keepf = sKeep[row];
            float* dst = out_fea + ((size_t)n * FAN + k) * COUT + bn + warp_n
                       + (lane & 3) * 2;
            #pragma unroll
            for (int nt = 0; nt < 8; nt++) {
                float2 v;
                v.x = (acc[mt][nt][h * 2 + 0] + bb[nt].x) * keepf;
                v.y = (acc[mt][nt][h * 2 + 1] + bb[nt].y) * keepf;
                *reinterpret_cast<float2*>(dst + nt * 8) = v;
            }
        }
}

// ------------------------------- launch ------------------------------------
extern "C" void kernel_launch(void* const* d_in, const int* in_sizes, int n_in,
                              void* d_out, int out_size) {
    const float* fea  = (const float*)d_in[0];
    const float* Wup  = (const float*)d_in[1];
    const float* bup  = (const float*)d_in[2];
    const float* Wcls = (const float*)d_in[3];
    const float* bcls = (const float*)d_in[4];
    const int*   idx  = (const int*)d_in[5];

    float* out       = (float*)d_out;
    float* out_fea   = out;                       // [400000, 256]
    float* out_exist = out + FEA_ELEMS;           // [400000]
    float* out_tgt   = out + FEA_ELEMS + NUP;     // [400000]

    fused_pre_kernel<<<769, 256>>>(Wup, Wcls, bup, bcls, idx);      // idx 0
    exist_split_kernel<<<NPAR / 8, 256>>>(fea, out_exist, out_tgt); // idx 1
    scatter_target_kernel<<<(NTGT + 255) / 256, 256>>>(idx, out_tgt); // idx 2

    cudaFuncSetAttribute(upsample_hmma_kernel,
                         cudaFuncAttributeMaxDynamicSharedMemorySize, SMEM_TOTAL);
    dim3 grid(16, MTILES);
    upsample_hmma_kernel<<<grid, 256, SMEM_TOTAL>>>(bup, out_fea);  // idx 3
}

// round 17
// speedup vs baseline: 1.0656x; 1.0656x over previous
#include <cuda_runtime.h>
#include <cuda_bf16.h>
#include <cstdint>

// ---------------------------------------------------------------------------
// AbstractGenerativeUpsample — R17: R13 skeleton + B-fragment double buffer
//   fea[50000,256] f32, W_up[8,256,256] f32, b_up[256], W_cls[256,1], b_cls[1]
//   target_idx[200000] int64 (or int32; runtime-detected)
// Output (concat f32): fea_pruned[400000,256] | exist[400000] | target[400000]
//
// 4 launches: fused_pre -> exist_split -> scatter -> GEMM (ncu capture slot 3).
// GEMM: fea_up = fea @ W_k via Ahi*Bhi + Ahi*Blo + Alo*Bhi (bf16 split, fp32
// accumulate; residual ~1e-5). keep from exact fp32 de-fused exist path.
// ---------------------------------------------------------------------------

#define NPAR  50000
#define CIN   256
#define COUT  256
#define FAN   8
#define NUP   (NPAR * FAN)          // 400000
#define NTGT  200000
#define FEA_ELEMS 102400000LL

#define BM 128
#define BN 128
#define BK 32                        // bf16 per chunk
#define NCHUNK (CIN / BK)            // 8
#define MTILES ((NPAR + BM - 1) / BM)  // 391

// Padded smem rows: 40 bf16 = 80B stride -> ldmatrix conflict-free
#define ASTR  40
#define ATILE (128 * ASTR * 2)       // 10240 B per tile
#define BUFSZ (4 * ATILE)            // Ahi|Alo|Bhi|Blo = 40960 B
#define SM_KEEP (2 * BUFSZ)          // 81920
#define SMEM_TOTAL (SM_KEEP + 512)   // 82432  (x2 CTAs = 164 KB <= 228 KB)

// ------------------------- device scratch (no allocs) ----------------------
__device__ __align__(256) __nv_bfloat16 g_fea_hi[NPAR * CIN];
__device__ __align__(256) __nv_bfloat16 g_fea_lo[NPAR * CIN];
__device__ __align__(256) __nv_bfloat16 g_wt_hi[FAN * COUT * CIN];  // [k][n][c]
__device__ __align__(256) __nv_bfloat16 g_wt_lo[FAN * COUT * CIN];
__device__ float         g_Wv[FAN * COUT];
__device__ float         g_c0;
__device__ unsigned char g_keep[NUP];
__device__ int           g_idx_stride;

// ------------------------------ helpers ------------------------------------
__device__ __forceinline__ uint32_t smem_u32(const void* p) {
    uint32_t a;
    asm("{ .reg .u64 t; cvta.to.shared.u64 t, %1; cvt.u32.u64 %0, t; }"
        : "=r"(a) : "l"(p));
    return a;
}
__device__ __forceinline__ void cp16(uint32_t smem_dst, const void* gsrc) {
    asm volatile("cp.async.cg.shared.global [%0], [%1], 16;\n"
                 :: "r"(smem_dst), "l"(gsrc));
}
__device__ __forceinline__ void cp_commit() {
    asm volatile("cp.async.commit_group;\n" ::: "memory");
}
template <int N>
__device__ __forceinline__ void cp_wait() {
    asm volatile("cp.async.wait_group %0;\n" :: "n"(N) : "memory");
}
__device__ __forceinline__ void ldsm_x4(uint32_t* r, uint32_t addr) {
    asm volatile("ldmatrix.sync.aligned.m8n8.x4.shared.b16 {%0,%1,%2,%3}, [%4];"
                 : "=r"(r[0]), "=r"(r[1]), "=r"(r[2]), "=r"(r[3]) : "r"(addr));
}
__device__ __forceinline__ void mma_bf16(float* d, const uint32_t* a,
                                         const uint32_t* b) {
    asm volatile(
        "mma.sync.aligned.m16n8k16.row.col.f32.bf16.bf16.f32 "
        "{%0,%1,%2,%3}, {%4,%5,%6,%7}, {%8,%9}, {%0,%1,%2,%3};"
        : "+f"(d[0]), "+f"(d[1]), "+f"(d[2]), "+f"(d[3])
        : "r"(a[0]), "r"(a[1]), "r"(a[2]), "r"(a[3]), "r"(b[0]), "r"(b[1]));
}

// ------------- fused pre-kernel: detect | c0 | Wv | split_w ----------------
__global__ void fused_pre_kernel(const float* __restrict__ Wup,
                                 const float* __restrict__ Wcls,
                                 const float* __restrict__ bup,
                                 const float* __restrict__ bcls,
                                 const int* __restrict__ idx32) {
    __shared__ float sW[COUT];
    const int tid = threadIdx.x;
    const int bx = blockIdx.x;
    if (bx == 0) {
        if (tid == 0) {
            int allzero = 1;
            #pragma unroll 1
            for (int i = 0; i < 64; i++) {
                if (idx32[2 * (i * 512) + 1] != 0) { allzero = 0; break; }
            }
            g_idx_stride = allzero ? 2 : 1;
        } else if (tid >= 32 && tid < 64) {
            const int lane = tid - 32;
            float p = 0.0f;
            #pragma unroll
            for (int j = 0; j < 8; j++)
                p = fmaf(bup[lane + 32 * j], Wcls[lane + 32 * j], p);
            #pragma unroll
            for (int off = 16; off > 0; off >>= 1)
                p += __shfl_xor_sync(0xFFFFFFFFu, p, off);
            if (lane == 0) g_c0 = p + bcls[0];
        }
        return;
    }
    if (bx <= 256) {                         // Wv[k][c] = Wk[c][:] . Wcls
        const int b = bx - 1;
        if (tid < COUT) sW[tid] = Wcls[tid];
        __syncthreads();
        const int k = b >> 5;
        const int c = ((b & 31) << 3) + (tid >> 5);
        const int lane = tid & 31;
        const float* row = Wup + ((size_t)k * COUT + c) * CIN;
        float p = 0.0f;
        #pragma unroll
        for (int j = 0; j < 8; j++)
            p = fmaf(row[lane + 32 * j], sW[lane + 32 * j], p);
        #pragma unroll
        for (int off = 16; off > 0; off >>= 1)
            p += __shfl_xor_sync(0xFFFFFFFFu, p, off);
        if (lane == 0) g_Wv[k * COUT + c] = p;
        return;
    }
    // split_w: Wt[k][n][c] = split(W[k][c][n]); blocks 257..768
    const int base = (bx - 257) * 1024 + tid * 4;
    #pragma unroll
    for (int j = 0; j < 4; j++) {
        int t = base + j;
        int k = t >> 16, r = t & 65535, n = r >> 8, c = r & 255;
        float x = Wup[(k << 16) + (c << 8) + n];
        __nv_bfloat16 hi = __float2bfloat16_rn(x);
        __nv_bfloat16 lo = __float2bfloat16_rn(x - __bfloat162float(hi));
        g_wt_hi[t] = hi;
        g_wt_lo[t] = lo;
    }
}

// ---- exist (+keep, +tgt zero) fused with fea hi/lo split: one fea read ----
__global__ __launch_bounds__(256)
void exist_split_kernel(const float* __restrict__ fea,
                        float* __restrict__ out_exist,
                        float* __restrict__ out_tgt) {
    __shared__ float sWv[FAN * COUT];
    const int tid = threadIdx.x;
    #pragma unroll
    for (int j = 0; j < FAN * COUT / 256; j++) sWv[tid + 256 * j] = g_Wv[tid + 256 * j];
    __syncthreads();
    const int w = tid >> 5, lane = tid & 31;
    const int n = blockIdx.x * 8 + w;
    const float c0 = g_c0;
    float f[8];
    const float* frow = fea + (size_t)n * CIN;
    #pragma unroll
    for (int j = 0; j < 8; j++) f[j] = frow[lane + 32 * j];
    #pragma unroll
    for (int j = 0; j < 8; j++) {
        __nv_bfloat16 hi = __float2bfloat16_rn(f[j]);
        __nv_bfloat16 lo = __float2bfloat16_rn(f[j] - __bfloat162float(hi));
        g_fea_hi[(size_t)n * CIN + lane + 32 * j] = hi;
        g_fea_lo[(size_t)n * CIN + lane + 32 * j] = lo;
    }
    float mye = 0.0f;
    #pragma unroll
    for (int k = 0; k < FAN; k++) {
        float p = 0.0f;
        #pragma unroll
        for (int j = 0; j < 8; j++) p = fmaf(f[j], sWv[k * COUT + lane + 32 * j], p);
        #pragma unroll
        for (int off = 16; off > 0; off >>= 1)
            p += __shfl_xor_sync(0xFFFFFFFFu, p, off);
        if (lane == k) mye = p + c0;
    }
    if (lane < FAN) {
        const size_t g = (size_t)n * FAN + lane;
        out_exist[g] = mye;
        out_tgt[g] = 0.0f;
        g_keep[g] = (mye > 0.0f) ? 1 : 0;
    }
}

// ----------------------------- target scatter ------------------------------
__global__ void scatter_target_kernel(const int* __restrict__ idx32,
                                      float* __restrict__ tgt) {
    int i = blockIdx.x * blockDim.x + threadIdx.x;
    if (i < NTGT) {
        int s = g_idx_stride;
        int v = idx32[i * s];
        if (v >= 0 && v < NUP) { tgt[v] = 1.0f; g_keep[v] = 1; }
    }
}

// --------------------------- main HMMA GEMM --------------------------------
// grid (16, 391): bx -> {k = bx&7, ntile = bx>>3}; by = m tile. 256 threads,
// 8 warps as 4x2 -> warp tile 32x64. BK=32 depth-2 pipeline (R13 skeleton)
// + B-fragment double buffer: B[p+1] LDSMs issued before B[p]'s MMA bundle,
// so the LSU and tensor pipes overlap within each warp.
__global__ __launch_bounds__(256, 2)
void upsample_hmma_kernel(const float* __restrict__ bup,
                          float* __restrict__ out_fea) {
    extern __shared__ __align__(1024) char smem[];
    const uint32_t sb = smem_u32(smem);
    const int tid  = threadIdx.x;
    const int wid  = tid >> 5;
    const int lane = tid & 31;
    const int k    = blockIdx.x & 7;
    const int bn   = (blockIdx.x >> 3) * BN;
    const int nb   = blockIdx.y * BM;

    const int warp_m = (wid >> 1) * 32;
    const int warp_n = (wid & 1) * 64;

    float* sKeep = (float*)(smem + SM_KEEP);
    if (tid < BM) {
        const int n = nb + tid;
        sKeep[tid] = (n < NPAR && g_keep[(size_t)n * FAN + k]) ? 1.0f : 0.0f;
    }

    const int s0row = tid >> 2, s0c = (tid & 3);
    const int s1row = (tid + 256) >> 2, s1c = s0c;
    int an0 = nb + s0row; if (an0 >= NPAR) an0 = NPAR - 1;
    int an1 = nb + s1row; if (an1 >= NPAR) an1 = NPAR - 1;
    const size_t aoff0 = (size_t)an0 * CIN + s0c * 8;
    const size_t aoff1 = (size_t)an1 * CIN + s1c * 8;
    const size_t boff0 = ((size_t)k * COUT + bn + s0row) * CIN + s0c * 8;
    const size_t boff1 = ((size_t)k * COUT + bn + s1row) * CIN + s1c * 8;
    const uint32_t sd0 = s0row * (ASTR * 2) + s0c * 16;
    const uint32_t sd1 = s1row * (ASTR * 2) + s1c * 16;

    float acc[2][8][4];
    #pragma unroll
    for (int mt = 0; mt < 2; mt++)
        #pragma unroll
        for (int nt = 0; nt < 8; nt++)
            #pragma unroll
            for (int j = 0; j < 4; j++) acc[mt][nt][j] = 0.0f;

    {
        cp16(sb + sd0,              g_fea_hi + aoff0);
        cp16(sb + sd1,              g_fea_hi + aoff1);
        cp16(sb + ATILE + sd0,      g_fea_lo + aoff0);
        cp16(sb + ATILE + sd1,      g_fea_lo + aoff1);
        cp16(sb + 2 * ATILE + sd0,  g_wt_hi + boff0);
        cp16(sb + 2 * ATILE + sd1,  g_wt_hi + boff1);
        cp16(sb + 3 * ATILE + sd0,  g_wt_lo + boff0);
        cp16(sb + 3 * ATILE + sd1,  g_wt_lo + boff1);
        cp_commit();
    }

    const int a_row = (lane & 15);
    const int a_kh  = ((lane >> 4) & 1) * 8;
    const int b_row = (lane & 7) + ((lane >> 4) & 1) * 8;
    const int b_kh  = ((lane >> 3) & 1) * 8;

    #pragma unroll 1
    for (int t = 0; t < NCHUNK; t++) {
        const uint32_t base = sb + (uint32_t)(t & 1) * BUFSZ;
        if (t + 1 < NCHUNK) {
            const uint32_t nb2 = sb + (uint32_t)((t + 1) & 1) * BUFSZ;
            const size_t kc = (size_t)(t + 1) * BK;
            cp16(nb2 + sd0,             g_fea_hi + aoff0 + kc);
            cp16(nb2 + sd1,             g_fea_hi + aoff1 + kc);
            cp16(nb2 + ATILE + sd0,     g_fea_lo + aoff0 + kc);
            cp16(nb2 + ATILE + sd1,     g_fea_lo + aoff1 + kc);
            cp16(nb2 + 2 * ATILE + sd0, g_wt_hi + boff0 + kc);
            cp16(nb2 + 2 * ATILE + sd1, g_wt_hi + boff1 + kc);
            cp16(nb2 + 3 * ATILE + sd0, g_wt_lo + boff0 + kc);
            cp16(nb2 + 3 * ATILE + sd1, g_wt_lo + boff1 + kc);
            cp_commit();
            cp_wait<1>();
        } else {
            cp_wait<0>();
        }
        __syncthreads();

        #pragma unroll
        for (int kk = 0; kk < BK; kk += 16) {
            uint32_t ah[2][4], al[2][4];
            #pragma unroll
            for (int mt = 0; mt < 2; mt++) {
                const uint32_t ao =
                    ((warp_m + mt * 16 + a_row) * ASTR + kk + a_kh) * 2;
                ldsm_x4(ah[mt], base + ao);
                ldsm_x4(al[mt], base + ATILE + ao);
            }
            // B-fragment double buffer: load p=0, then prefetch p+1 before
            // each MMA bundle.
            uint32_t bh[2][4], bl[2][4];
            {
                const uint32_t bo0 =
                    ((warp_n + 0 * 16 + b_row) * ASTR + kk + b_kh) * 2;
                ldsm_x4(bh[0], base + 2 * ATILE + bo0);
                ldsm_x4(bl[0], base + 3 * ATILE + bo0);
            }
            #pragma unroll
            for (int p = 0; p < 4; p++) {
                const int cur = p & 1, nxt = cur ^ 1;
                if (p < 3) {
                    const uint32_t bo =
                        ((warp_n + (p + 1) * 16 + b_row) * ASTR + kk + b_kh) * 2;
                    ldsm_x4(bh[nxt], base + 2 * ATILE + bo);
                    ldsm_x4(bl[nxt], base + 3 * ATILE + bo);
                }
                #pragma unroll
                for (int mt = 0; mt < 2; mt++) {
                    #pragma unroll
                    for (int half = 0; half < 2; half++) {
                        float* d = acc[mt][2 * p + half];
                        mma_bf16(d, ah[mt], &bh[cur][2 * half]);
                        mma_bf16(d, ah[mt], &bl[cur][2 * half]);
                        mma_bf16(d, al[mt], &bh[cur][2 * half]);
                    }
                }
            }
        }
        __syncthreads();
    }

    // ---- epilogue: +b_up, mask by keep, store ----
    float2 bb[8];
    #pragma unroll
    for (int nt = 0; nt < 8; nt++)
        bb[nt] = *reinterpret_cast<const float2*>(
            bup + bn + warp_n + nt * 8 + (lane & 3) * 2);

    #pragma unroll
    for (int mt = 0; mt < 2; mt++)
        #pragma unroll
        for (int h = 0; h < 2; h++) {
            const int row = warp_m + mt * 16 + (lane >> 2) + h * 8;
            const int n = nb + row;
            if (n >= NPAR) continue;
            const float keepf = sKeep[row];
            float* dst = out_fea + ((size_t)n * FAN + k) * COUT + bn + warp_n
                       + (lane & 3) * 2;
            #pragma unroll
            for (int nt = 0; nt < 8; nt++) {
                float2 v;
                v.x = (acc[mt][nt][h * 2 + 0] + bb[nt].x) * keepf;
                v.y = (acc[mt][nt][h * 2 + 1] + bb[nt].y) * keepf;
                *reinterpret_cast<float2*>(dst + nt * 8) = v;
            }
        }
}

// ------------------------------- launch ------------------------------------
extern "C" void kernel_launch(void* const* d_in, const int* in_sizes, int n_in,
                              void* d_out, int out_size) {
    const float* fea  = (const float*)d_in[0];
    const float* Wup  = (const float*)d_in[1];
    const float* bup  = (const float*)d_in[2];
    const float* Wcls = (const float*)d_in[3];
    const float* bcls = (const float*)d_in[4];
    const int*   idx  = (const int*)d_in[5];

    float* out       = (float*)d_out;
    float* out_fea   = out;                       // [400000, 256]
    float* out_exist = out + FEA_ELEMS;           // [400000]
    float* out_tgt   = out + FEA_ELEMS + NUP;     // [400000]

    fused_pre_kernel<<<769, 256>>>(Wup, Wcls, bup, bcls, idx);      // idx 0
    exist_split_kernel<<<NPAR / 8, 256>>>(fea, out_exist, out_tgt); // idx 1
    scatter_target_kernel<<<(NTGT + 255) / 256, 256>>>(idx, out_tgt); // idx 2

    cudaFuncSetAttribute(upsample_hmma_kernel,
                         cudaFuncAttributeMaxDynamicSharedMemorySize, SMEM_TOTAL);
    dim3 grid(16, MTILES);
    upsample_hmma_kernel<<<grid, 256, SMEM_TOTAL>>>(bup, out_fea);  // idx 3
}